// round 12
// baseline (speedup 1.0000x reference)
#include <cuda_runtime.h>
#include <cuda_fp16.h>
#include <math.h>
#include <stdint.h>

#define B_  8
#define S_  1024
#define D_  768
#define H_  12
#define DH_ 64
#define F_  3072
#define NROWS (B_*S_)   /* 8192 */

#define EPI_NONE 0
#define EPI_GELU 1
#define EPI_ADD  2

// ---------------------------------------------------------------------------
// Scratch (device globals — no allocation allowed)
// ---------------------------------------------------------------------------
__device__ __half g_h  [NROWS*D_];
__device__ __half g_q  [NROWS*D_];
__device__ __half g_k  [NROWS*D_];
__device__ __half g_v  [NROWS*D_];
__device__ __half g_ctx[NROWS*D_];
__device__ float  g_x2 [NROWS*D_];
__device__ __half g_ln2[NROWS*D_];
__device__ __half g_act[NROWS*F_];
// fp16 weights, NATURAL layout [K][N]
#define WT_Q  0
#define WT_K  (768*768)
#define WT_V  (2*768*768)
#define WT_O  (3*768*768)
#define WT_W1 (4*768*768)
#define WT_W2 (4*768*768 + 768*3072)
__device__ __half g_wt [4*768*768 + 2*768*3072];

// ---------------------------------------------------------------------------
// helpers
// ---------------------------------------------------------------------------
__device__ __forceinline__ float gelu_f(float x) {
    return 0.5f * x * (1.0f + erff(x * 0.70710678118654752f));
}

__device__ __forceinline__ void mma_f16(
    float c[4], const unsigned a[4], const unsigned b[2])
{
    asm volatile(
        "mma.sync.aligned.m16n8k16.row.col.f32.f16.f16.f32 "
        "{%0,%1,%2,%3}, {%4,%5,%6,%7}, {%8,%9}, {%0,%1,%2,%3};"
        : "+f"(c[0]), "+f"(c[1]), "+f"(c[2]), "+f"(c[3])
        : "r"(a[0]), "r"(a[1]), "r"(a[2]), "r"(a[3]),
          "r"(b[0]), "r"(b[1]));
}

__device__ __forceinline__ void ldsm_x4(
    unsigned& r0, unsigned& r1, unsigned& r2, unsigned& r3, unsigned addr)
{
    asm volatile("ldmatrix.sync.aligned.m8n8.x4.shared.b16 {%0,%1,%2,%3}, [%4];"
                 : "=r"(r0), "=r"(r1), "=r"(r2), "=r"(r3) : "r"(addr));
}

__device__ __forceinline__ void ldsm_x4_trans(
    unsigned& r0, unsigned& r1, unsigned& r2, unsigned& r3, unsigned addr)
{
    asm volatile("ldmatrix.sync.aligned.m8n8.x4.trans.shared.b16 {%0,%1,%2,%3}, [%4];"
                 : "=r"(r0), "=r"(r1), "=r"(r2), "=r"(r3) : "r"(addr));
}

__device__ __forceinline__ unsigned pack_h2(float a, float b) {
    __half2 t = __floats2half2_rn(a, b);
    return *(unsigned*)&t;
}

__device__ __forceinline__ void cp_async16(unsigned smem_addr, const void* gptr) {
    asm volatile("cp.async.cg.shared.global [%0], [%1], 16;"
                 :: "r"(smem_addr), "l"(gptr));
}
__device__ __forceinline__ void cp_commit() {
    asm volatile("cp.async.commit_group;");
}
template<int N>
__device__ __forceinline__ void cp_wait() {
    asm volatile("cp.async.wait_group %0;" :: "n"(N));
}

// ---------------------------------------------------------------------------
// Weight convert (fp32 -> fp16, natural layout). One launch for all 6.
// ---------------------------------------------------------------------------
__global__ __launch_bounds__(256) void convert_w_kernel(
    const float* __restrict__ Wq, const float* __restrict__ Wk,
    const float* __restrict__ Wv, const float* __restrict__ Wo,
    const float* __restrict__ W1, const float* __restrict__ W2,
    __half* __restrict__ out)
{
    const int n1 = 768*768/2;
    const int n2 = 768*3072/2;
    const int total = 4*n1 + 2*n2;
    for (int i = blockIdx.x*blockDim.x + threadIdx.x; i < total;
         i += gridDim.x*blockDim.x) {
        const float2* src; int off;
        if (i < 4*n1) {
            int w = i / n1; off = i - w*n1;
            src = (const float2*)((w==0)?Wq:(w==1)?Wk:(w==2)?Wv:Wo);
        } else if (i < 4*n1 + n2) {
            src = (const float2*)W1; off = i - 4*n1;
        } else {
            src = (const float2*)W2; off = i - 4*n1 - n2;
        }
        float2 f = src[off];
        ((__half2*)out)[i] = __floats2half2_rn(f.x, f.y);
    }
}

// ---------------------------------------------------------------------------
// LayerNorm: warp-per-row, 8 rows/block, shuffle-only reduction.
// ---------------------------------------------------------------------------
__global__ __launch_bounds__(256) void ln_kernel(
    const float* __restrict__ x, const float* __restrict__ gam,
    const float* __restrict__ bet, __half* __restrict__ out)
{
    int warp = threadIdx.x >> 5, lane = threadIdx.x & 31;
    int row = blockIdx.x * 8 + warp;
    const float4* xr = (const float4*)(x + (size_t)row * D_);

    float4 vv[6];
    float s = 0.f, ss = 0.f;
    #pragma unroll
    for (int c = 0; c < 6; c++) {
        float4 t = xr[c*32 + lane];
        vv[c] = t;
        s  += t.x + t.y + t.z + t.w;
        ss += t.x*t.x + t.y*t.y + t.z*t.z + t.w*t.w;
    }
    #pragma unroll
    for (int o = 16; o > 0; o >>= 1) {
        s  += __shfl_xor_sync(0xffffffffu, s,  o);
        ss += __shfl_xor_sync(0xffffffffu, ss, o);
    }
    float mu  = s * (1.0f / D_);
    float var = ss * (1.0f / D_) - mu * mu;
    float inv = rsqrtf(var + 1e-6f);

    uint2* orow = (uint2*)(out + (size_t)row * D_);
    const float4* gg4 = (const float4*)gam;
    const float4* bb4 = (const float4*)bet;
    #pragma unroll
    for (int c = 0; c < 6; c++) {
        int idx = c*32 + lane;
        float4 gg = gg4[idx], bb = bb4[idx];
        float4 t = vv[c];
        float v0 = (t.x - mu) * inv * gg.x + bb.x;
        float v1 = (t.y - mu) * inv * gg.y + bb.y;
        float v2 = (t.z - mu) * inv * gg.z + bb.z;
        float v3 = (t.w - mu) * inv * gg.w + bb.w;
        uint2 o2;
        o2.x = pack_h2(v0, v1);
        o2.y = pack_h2(v2, v3);
        orow[idx] = o2;
    }
}

// ---------------------------------------------------------------------------
// fp16 tensor-core GEMM: 256x128 CTA tile, BK=64, 512 threads (16 warps),
// warp tile 32x64 (unchanged, validated). A smem [m][k] stride 72 (ldmatrix);
// B natural W [K][N], smem [k][n] stride 136 (trans-ldmatrix). 3-stage cp.async.
// ---------------------------------------------------------------------------
#define BK 64
#define TMROWS 256
#define LDAH 72
#define LDBH 136
#define A_STG_H (TMROWS*LDAH)     /* 18432 halves */
#define B_STG_H (64*LDBH)         /* 8704 halves */
#define NSTG 3
#define GEMM_SMEM_BYTES (NSTG*(A_STG_H + B_STG_H)*2)   /* 162816 B */

template<int EPI>
__device__ __forceinline__ void h_gemm_body(
    const __half* __restrict__ A, const __half* __restrict__ W,
    const float* __restrict__ bias, const float* __restrict__ res,
    void* __restrict__ Cout, int M, int N, int K)
{
    extern __shared__ __half hsm[];
    __half* As = hsm;
    __half* Bs = hsm + NSTG * A_STG_H;

    int tid  = threadIdx.x;
    int bm = blockIdx.y * TMROWS, bn = blockIdx.x * 128;
    int lane = tid & 31, warp = tid >> 5;
    int warp_m = warp >> 1;            // 0..7
    int warp_n = warp & 1;             // 0..1
    int g  = lane >> 2;
    int tg = lane & 3;

    unsigned a_su[NSTG], b_su[NSTG];
    #pragma unroll
    for (int s = 0; s < NSTG; s++) {
        a_su[s] = (unsigned)__cvta_generic_to_shared(As + s * A_STG_H);
        b_su[s] = (unsigned)__cvta_generic_to_shared(Bs + s * B_STG_H);
    }

    int arow_off = (lane & 7) + ((lane >> 3) & 1) * 8;
    int ak_off   = ((lane >> 4) & 1) * 8;
    unsigned a_lm[2];
    #pragma unroll
    for (int mt = 0; mt < 2; mt++)
        a_lm[mt] = (unsigned)(((warp_m * 32 + mt * 16 + arow_off) * LDAH + ak_off) * 2);

    int trow = (lane & 7) + ((lane >> 3) & 1) * 8;
    int tcol = ((lane >> 4) & 1) * 8;
    unsigned b_lm[4];
    #pragma unroll
    for (int dp = 0; dp < 4; dp++)
        b_lm[dp] = (unsigned)((trow * LDBH + warp_n * 64 + dp * 16 + tcol) * 2);

    float acc[2][8][4];
    #pragma unroll
    for (int mt = 0; mt < 2; mt++)
        #pragma unroll
        for (int nt = 0; nt < 8; nt++)
            #pragma unroll
            for (int i = 0; i < 4; i++) acc[mt][nt][i] = 0.f;

    int nck = K / BK;

    auto issue = [&](int st, int ck) {
        int kb = ck * BK;
        // A: 256 rows x 64 halves = 2048 16B chunks / 512 threads = 4 each
        #pragma unroll
        for (int p = 0; p < 4; p++) {
            int cid = tid + p * 512;
            int row = cid >> 3, c = cid & 7;
            unsigned off = (unsigned)((row * LDAH + c * 8) * 2);
            cp_async16(a_su[st] + off, A + (size_t)(bm + row) * K + kb + c * 8);
        }
        // B: 64 k-rows x 128 n-cols = 1024 16B chunks / 512 threads = 2 each
        #pragma unroll
        for (int p = 0; p < 2; p++) {
            int cid = tid + p * 512;
            int row = cid >> 4, c = cid & 15;
            unsigned off = (unsigned)((row * LDBH + c * 8) * 2);
            cp_async16(b_su[st] + off, W + (size_t)(kb + row) * N + bn + c * 8);
        }
        cp_commit();
    };

    issue(0, 0);
    if (nck > 1) issue(1, 1);

    for (int ck = 0; ck < nck; ck++) {
        int st = ck % 3;
        if (ck + 1 < nck) cp_wait<1>(); else cp_wait<0>();
        __syncthreads();
        if (ck + 2 < nck) issue((ck + 2) % 3, ck + 2);

        unsigned abase = a_su[st], bbase = b_su[st];

        #pragma unroll
        for (int ks = 0; ks < 4; ks++) {
            unsigned kadd_a = (unsigned)(ks * 16 * 2);
            unsigned kadd_b = (unsigned)(ks * 16 * LDBH * 2);
            unsigned af[2][4], bf[8][2];
            #pragma unroll
            for (int mt = 0; mt < 2; mt++)
                ldsm_x4(af[mt][0], af[mt][1], af[mt][2], af[mt][3],
                        abase + a_lm[mt] + kadd_a);
            #pragma unroll
            for (int dp = 0; dp < 4; dp++)
                ldsm_x4_trans(bf[2*dp][0], bf[2*dp][1], bf[2*dp+1][0], bf[2*dp+1][1],
                              bbase + b_lm[dp] + kadd_b);
            #pragma unroll
            for (int mt = 0; mt < 2; mt++)
                #pragma unroll
                for (int nt = 0; nt < 8; nt++)
                    mma_f16(acc[mt][nt], af[mt], bf[nt]);
        }
    }
    __syncthreads();

    #pragma unroll
    for (int mt = 0; mt < 2; mt++) {
        #pragma unroll
        for (int nt = 0; nt < 8; nt++) {
            int row0 = bm + warp_m * 32 + mt * 16 + g;
            int row1 = row0 + 8;
            int col  = bn + warp_n * 64 + nt * 8 + tg * 2;
            float2 bb = *(const float2*)&bias[col];
            float v0 = acc[mt][nt][0] + bb.x;
            float v1 = acc[mt][nt][1] + bb.y;
            float v2 = acc[mt][nt][2] + bb.x;
            float v3 = acc[mt][nt][3] + bb.y;
            if (EPI == EPI_GELU) {
                v0 = gelu_f(v0); v1 = gelu_f(v1);
                v2 = gelu_f(v2); v3 = gelu_f(v3);
            }
            if (EPI == EPI_ADD) {
                float* C = (float*)Cout;
                float2 r0 = *(const float2*)&res[(size_t)row0 * N + col];
                float2 r1 = *(const float2*)&res[(size_t)row1 * N + col];
                v0 += r0.x; v1 += r0.y; v2 += r1.x; v3 += r1.y;
                *(float2*)&C[(size_t)row0 * N + col] = make_float2(v0, v1);
                *(float2*)&C[(size_t)row1 * N + col] = make_float2(v2, v3);
            } else {
                __half* C = (__half*)Cout;
                *(__half2*)&C[(size_t)row0 * N + col] = __floats2half2_rn(v0, v1);
                *(__half2*)&C[(size_t)row1 * N + col] = __floats2half2_rn(v2, v3);
            }
        }
    }
}

template<int EPI>
__global__ __launch_bounds__(512, 1) void h_gemm_kernel(
    const __half* __restrict__ A, const __half* __restrict__ W,
    const float* __restrict__ bias, const float* __restrict__ res,
    void* __restrict__ Cout, int M, int N, int K)
{
    h_gemm_body<EPI>(A, W, bias, res, Cout, M, N, K);
}

__global__ __launch_bounds__(512, 1) void h_qkv_kernel(
    const __half* __restrict__ A, const __half* __restrict__ wt,
    const float* __restrict__ bq, const float* __restrict__ bk, const float* __restrict__ bv,
    __half* __restrict__ Cq, __half* __restrict__ Ck, __half* __restrict__ Cv)
{
    const __half* W   = wt + (size_t)blockIdx.z * (768 * 768);
    const float*  bia = (blockIdx.z == 0) ? bq : (blockIdx.z == 1) ? bk : bv;
    __half*       C   = (blockIdx.z == 0) ? Cq : (blockIdx.z == 1) ? Ck : Cv;
    h_gemm_body<EPI_NONE>(A, W, bia, nullptr, (void*)C, NROWS, D_, D_);
}

// ---------------------------------------------------------------------------
// Fused attention, register flash (validated R9) + cp.async double-buffered
// K/V tiles: tile kt+1 loads issued before computing tile kt.
// Dynamic smem: Qh[128][72] + Kh[2][64][72] + Vh[2][64][72] = 55296 B.
// ---------------------------------------------------------------------------
#define LQ 72
struct AttnSmem {
    __half Qh[128][LQ];
    __half Kh[2][64][LQ];
    __half Vh[2][64][LQ];
};
#define ATTN_SMEM_BYTES ((int)sizeof(AttnSmem))

__global__ __launch_bounds__(256) void attn_kernel(
    const __half* __restrict__ q, const __half* __restrict__ k,
    const __half* __restrict__ v, __half* __restrict__ ctx)
{
    extern __shared__ char smem_raw[];
    AttnSmem& S = *(AttnSmem*)smem_raw;
    int bb = blockIdx.z, hh = blockIdx.y;
    int q0 = blockIdx.x * 128;
    int tid = threadIdx.x;
    int lane = tid & 31, wid = tid >> 5;
    int g = lane >> 2, tg = lane & 3;
    int m0 = wid * 16;

    unsigned k_su[2], v_su[2];
    #pragma unroll
    for (int bi = 0; bi < 2; bi++) {
        k_su[bi] = (unsigned)__cvta_generic_to_shared(&S.Kh[bi][0][0]);
        v_su[bi] = (unsigned)__cvta_generic_to_shared(&S.Vh[bi][0][0]);
    }

    // issue cp.async loads of K/V tile kt into buffer bi
    auto issue_kv = [&](int bi, int kt) {
        int k0g = kt * 64;
        #pragma unroll
        for (int i = 0; i < 2; i++) {
            int cid = tid + i * 256;
            int row = cid >> 3, c = cid & 7;
            unsigned off = (unsigned)((row * LQ + c * 8) * 2);
            size_t base = ((size_t)((bb*S_ + k0g + row)*H_ + hh))*DH_ + c*8;
            cp_async16(k_su[bi] + off, k + base);
            cp_async16(v_su[bi] + off, v + base);
        }
        cp_commit();
    };

    // load Q (scaled by 1/8)
    {
        const __half2 sc = __half2half2(__float2half(0.125f));
        #pragma unroll
        for (int i = 0; i < 4; i++) {
            int cid = tid + i * 256;
            int row = cid >> 3, c = cid & 7;
            const __half* gq = q + ((size_t)((bb*S_ + q0 + row)*H_ + hh))*DH_ + c*8;
            uint4 t = *(const uint4*)gq;
            __half2* hp = (__half2*)&t;
            #pragma unroll
            for (int j = 0; j < 4; j++) hp[j] = __hmul2(hp[j], sc);
            *(uint4*)&S.Qh[row][c*8] = t;
        }
    }
    issue_kv(0, 0);

    int arow = (lane & 7) + ((lane >> 3) & 1) * 8;
    int acol = ((lane >> 4) & 1) * 8;
    int brow = (lane & 7) + ((lane >> 4) & 1) * 8;
    int bcol = ((lane >> 3) & 1) * 8;

    unsigned q_lm = (unsigned)__cvta_generic_to_shared(&S.Qh[m0 + arow][acol]);
    unsigned k_lm[2][4], v_lm[2][4][4];
    #pragma unroll
    for (int bi = 0; bi < 2; bi++) {
        #pragma unroll
        for (int p = 0; p < 4; p++)
            k_lm[bi][p] = (unsigned)__cvta_generic_to_shared(
                &S.Kh[bi][p*16 + brow][bcol]);
        #pragma unroll
        for (int ks = 0; ks < 4; ks++)
            #pragma unroll
            for (int dp = 0; dp < 4; dp++)
                v_lm[bi][ks][dp] = (unsigned)__cvta_generic_to_shared(
                    &S.Vh[bi][ks*16 + arow][dp*16 + acol]);
    }

    float m_r[2] = {-1e30f, -1e30f};
    float l_r[2] = {0.f, 0.f};
    float o[8][4];
    #pragma unroll
    for (int nt = 0; nt < 8; nt++)
        #pragma unroll
        for (int i = 0; i < 4; i++) o[nt][i] = 0.f;

    __syncthreads();

    unsigned aq[4][4];
    #pragma unroll
    for (int ks = 0; ks < 4; ks++)
        ldsm_x4(aq[ks][0], aq[ks][1], aq[ks][2], aq[ks][3], q_lm + ks*32);

    const int NKT = S_/64;
    for (int kt = 0; kt < NKT; kt++) {
        int bi = kt & 1;
        // issue next tile into the other buffer (free: compute kt-1 done +
        // end-of-previous-iteration barrier passed)
        if (kt + 1 < NKT) {
            issue_kv(bi ^ 1, kt + 1);
            cp_wait<1>();     // tile kt complete; kt+1 still in flight
        } else {
            cp_wait<0>();
        }
        __syncthreads();

        // ---- QK^T ----
        float s[8][4];
        #pragma unroll
        for (int nt = 0; nt < 8; nt++)
            #pragma unroll
            for (int i = 0; i < 4; i++) s[nt][i] = 0.f;
        #pragma unroll
        for (int ks = 0; ks < 4; ks++) {
            unsigned bf[8][2];
            #pragma unroll
            for (int p = 0; p < 4; p++)
                ldsm_x4(bf[2*p][0], bf[2*p][1], bf[2*p+1][0], bf[2*p+1][1],
                        k_lm[bi][p] + ks*32);
            #pragma unroll
            for (int nt = 0; nt < 8; nt++)
                mma_f16(s[nt], aq[ks], bf[nt]);
        }

        // ---- warp-local online softmax ----
        #pragma unroll
        for (int r = 0; r < 2; r++) {
            float mx = -1e30f;
            #pragma unroll
            for (int nt = 0; nt < 8; nt++)
                mx = fmaxf(mx, fmaxf(s[nt][2*r], s[nt][2*r+1]));
            mx = fmaxf(mx, __shfl_xor_sync(0xffffffffu, mx, 1));
            mx = fmaxf(mx, __shfl_xor_sync(0xffffffffu, mx, 2));
            float mn = fmaxf(m_r[r], mx);
            float cr = __expf(m_r[r] - mn);
            m_r[r] = mn;
            float ls = 0.f;
            #pragma unroll
            for (int nt = 0; nt < 8; nt++) {
                float p0 = __expf(s[nt][2*r    ] - mn);
                float p1 = __expf(s[nt][2*r + 1] - mn);
                s[nt][2*r] = p0; s[nt][2*r+1] = p1;
                ls += p0 + p1;
            }
            ls += __shfl_xor_sync(0xffffffffu, ls, 1);
            ls += __shfl_xor_sync(0xffffffffu, ls, 2);
            l_r[r] = l_r[r] * cr + ls;
            #pragma unroll
            for (int nt = 0; nt < 8; nt++) {
                o[nt][2*r] *= cr; o[nt][2*r+1] *= cr;
            }
        }

        unsigned pa[4][4];
        #pragma unroll
        for (int ks = 0; ks < 4; ks++) {
            pa[ks][0] = pack_h2(s[2*ks  ][0], s[2*ks  ][1]);
            pa[ks][1] = pack_h2(s[2*ks  ][2], s[2*ks  ][3]);
            pa[ks][2] = pack_h2(s[2*ks+1][0], s[2*ks+1][1]);
            pa[ks][3] = pack_h2(s[2*ks+1][2], s[2*ks+1][3]);
        }

        // ---- P*V ----
        #pragma unroll
        for (int ks = 0; ks < 4; ks++) {
            unsigned vf[8][2];
            #pragma unroll
            for (int dp = 0; dp < 4; dp++)
                ldsm_x4_trans(vf[2*dp][0], vf[2*dp][1], vf[2*dp+1][0], vf[2*dp+1][1],
                              v_lm[bi][ks][dp]);
            #pragma unroll
            for (int nt = 0; nt < 8; nt++)
                mma_f16(o[nt], pa[ks], vf[nt]);
        }
        __syncthreads();   // all warps done with buffer bi before it's reissued
    }

    float inv0 = 1.0f / l_r[0];
    float inv1 = 1.0f / l_r[1];
    int row0 = bb*S_ + q0 + m0 + g;
    int row1 = row0 + 8;
    #pragma unroll
    for (int nt = 0; nt < 8; nt++) {
        int d = nt * 8 + tg * 2;
        *(__half2*)&ctx[((size_t)(row0*H_ + hh))*DH_ + d] =
            __floats2half2_rn(o[nt][0] * inv0, o[nt][1] * inv0);
        *(__half2*)&ctx[((size_t)(row1*H_ + hh))*DH_ + d] =
            __floats2half2_rn(o[nt][2] * inv1, o[nt][3] * inv1);
    }
}

// ---------------------------------------------------------------------------
// Launcher
// ---------------------------------------------------------------------------
extern "C" void kernel_launch(void* const* d_in, const int* in_sizes, int n_in,
                              void* d_out, int out_size)
{
    const float* x   = (const float*)d_in[0];
    const float* Wq  = (const float*)d_in[1];
    const float* bq  = (const float*)d_in[2];
    const float* Wk  = (const float*)d_in[3];
    const float* bk  = (const float*)d_in[4];
    const float* Wv  = (const float*)d_in[5];
    const float* bv  = (const float*)d_in[6];
    const float* Wo  = (const float*)d_in[7];
    const float* bo  = (const float*)d_in[8];
    const float* g1  = (const float*)d_in[9];
    const float* be1 = (const float*)d_in[10];
    const float* g2  = (const float*)d_in[11];
    const float* be2 = (const float*)d_in[12];
    const float* W1  = (const float*)d_in[13];
    const float* b1  = (const float*)d_in[14];
    const float* W2  = (const float*)d_in[15];
    const float* b2  = (const float*)d_in[16];
    float* out = (float*)d_out;

    __half *h, *q, *k, *v, *ctx, *ln2, *act, *wt;
    float *x2;
    cudaGetSymbolAddress((void**)&h,   g_h);
    cudaGetSymbolAddress((void**)&q,   g_q);
    cudaGetSymbolAddress((void**)&k,   g_k);
    cudaGetSymbolAddress((void**)&v,   g_v);
    cudaGetSymbolAddress((void**)&ctx, g_ctx);
    cudaGetSymbolAddress((void**)&x2,  g_x2);
    cudaGetSymbolAddress((void**)&ln2, g_ln2);
    cudaGetSymbolAddress((void**)&act, g_act);
    cudaGetSymbolAddress((void**)&wt,  g_wt);

    cudaFuncSetAttribute(h_gemm_kernel<EPI_ADD>,
                         cudaFuncAttributeMaxDynamicSharedMemorySize, GEMM_SMEM_BYTES);
    cudaFuncSetAttribute(h_gemm_kernel<EPI_GELU>,
                         cudaFuncAttributeMaxDynamicSharedMemorySize, GEMM_SMEM_BYTES);
    cudaFuncSetAttribute(h_qkv_kernel,
                         cudaFuncAttributeMaxDynamicSharedMemorySize, GEMM_SMEM_BYTES);
    cudaFuncSetAttribute(attn_kernel,
                         cudaFuncAttributeMaxDynamicSharedMemorySize, ATTN_SMEM_BYTES);

    // 0. weight fp32->fp16 convert (natural layout), single launch
    convert_w_kernel<<<2048, 256>>>(Wq, Wk, Wv, Wo, W1, W2, wt);

    // 1. pre-LN -> fp16 h
    ln_kernel<<<NROWS/8, 256>>>(x, g1, be1, h);
    // 2. QKV (fp16 mma, batched) -> fp16 q,k,v
    dim3 gqkv(D_/128, NROWS/TMROWS, 3);
    h_qkv_kernel<<<gqkv, 512, GEMM_SMEM_BYTES>>>(h, wt, bq, bk, bv, q, k, v);
    // 3. fused attention (register flash + cp.async) -> fp16 ctx
    dim3 gat(S_/128, H_, B_);
    attn_kernel<<<gat, 256, ATTN_SMEM_BYTES>>>(q, k, v, ctx);
    // 4. Wo projection + residual -> fp32 x2
    dim3 go(D_/128, NROWS/TMROWS);
    h_gemm_kernel<EPI_ADD><<<go, 512, GEMM_SMEM_BYTES>>>(ctx, wt + WT_O, bo, x, (void*)x2, NROWS, D_, D_);
    // 5. LN2 -> fp16 ln2
    ln_kernel<<<NROWS/8, 256>>>(x2, g2, be2, ln2);
    // 6. MLP up + exact GELU -> fp16 act
    dim3 gup(F_/128, NROWS/TMROWS);
    h_gemm_kernel<EPI_GELU><<<gup, 512, GEMM_SMEM_BYTES>>>(ln2, wt + WT_W1, b1, nullptr, (void*)act, NROWS, F_, D_);
    // 7. MLP down + bias + residual -> fp32 out
    dim3 gdn(D_/128, NROWS/TMROWS);
    h_gemm_kernel<EPI_ADD><<<gdn, 512, GEMM_SMEM_BYTES>>>(act, wt + WT_W2, b2, x2, (void*)out, NROWS, D_, F_);
}

// round 13
// speedup vs baseline: 1.1819x; 1.1819x over previous
#include <cuda_runtime.h>
#include <cuda_fp16.h>
#include <math.h>
#include <stdint.h>

#define B_  8
#define S_  1024
#define D_  768
#define H_  12
#define DH_ 64
#define F_  3072
#define NROWS (B_*S_)   /* 8192 */

#define EPI_NONE 0
#define EPI_GELU 1
#define EPI_ADD  2

// ---------------------------------------------------------------------------
// Scratch (device globals — no allocation allowed)
// ---------------------------------------------------------------------------
__device__ __half g_h  [NROWS*D_];
__device__ __half g_q  [NROWS*D_];
__device__ __half g_k  [NROWS*D_];
__device__ __half g_v  [NROWS*D_];
__device__ __half g_ctx[NROWS*D_];
__device__ float  g_x2 [NROWS*D_];
__device__ __half g_ln2[NROWS*D_];
__device__ __half g_act[NROWS*F_];
// fp16 weights, NATURAL layout [K][N]
#define WT_Q  0
#define WT_K  (768*768)
#define WT_V  (2*768*768)
#define WT_O  (3*768*768)
#define WT_W1 (4*768*768)
#define WT_W2 (4*768*768 + 768*3072)
__device__ __half g_wt [4*768*768 + 2*768*3072];

// ---------------------------------------------------------------------------
// helpers
// ---------------------------------------------------------------------------
__device__ __forceinline__ float gelu_f(float x) {
    return 0.5f * x * (1.0f + erff(x * 0.70710678118654752f));
}

__device__ __forceinline__ void mma_f16(
    float c[4], const unsigned a[4], const unsigned b[2])
{
    asm volatile(
        "mma.sync.aligned.m16n8k16.row.col.f32.f16.f16.f32 "
        "{%0,%1,%2,%3}, {%4,%5,%6,%7}, {%8,%9}, {%0,%1,%2,%3};"
        : "+f"(c[0]), "+f"(c[1]), "+f"(c[2]), "+f"(c[3])
        : "r"(a[0]), "r"(a[1]), "r"(a[2]), "r"(a[3]),
          "r"(b[0]), "r"(b[1]));
}

__device__ __forceinline__ void ldsm_x4(
    unsigned& r0, unsigned& r1, unsigned& r2, unsigned& r3, unsigned addr)
{
    asm volatile("ldmatrix.sync.aligned.m8n8.x4.shared.b16 {%0,%1,%2,%3}, [%4];"
                 : "=r"(r0), "=r"(r1), "=r"(r2), "=r"(r3) : "r"(addr));
}

__device__ __forceinline__ void ldsm_x4_trans(
    unsigned& r0, unsigned& r1, unsigned& r2, unsigned& r3, unsigned addr)
{
    asm volatile("ldmatrix.sync.aligned.m8n8.x4.trans.shared.b16 {%0,%1,%2,%3}, [%4];"
                 : "=r"(r0), "=r"(r1), "=r"(r2), "=r"(r3) : "r"(addr));
}

__device__ __forceinline__ unsigned pack_h2(float a, float b) {
    __half2 t = __floats2half2_rn(a, b);
    return *(unsigned*)&t;
}

__device__ __forceinline__ void cp_async16(unsigned smem_addr, const void* gptr) {
    asm volatile("cp.async.cg.shared.global [%0], [%1], 16;"
                 :: "r"(smem_addr), "l"(gptr));
}
__device__ __forceinline__ void cp_commit() {
    asm volatile("cp.async.commit_group;");
}
template<int N>
__device__ __forceinline__ void cp_wait() {
    asm volatile("cp.async.wait_group %0;" :: "n"(N));
}

// ---------------------------------------------------------------------------
// Weight convert (fp32 -> fp16, natural layout). One launch for all 6.
// ---------------------------------------------------------------------------
__global__ __launch_bounds__(256) void convert_w_kernel(
    const float* __restrict__ Wq, const float* __restrict__ Wk,
    const float* __restrict__ Wv, const float* __restrict__ Wo,
    const float* __restrict__ W1, const float* __restrict__ W2,
    __half* __restrict__ out)
{
    const int n1 = 768*768/2;
    const int n2 = 768*3072/2;
    const int total = 4*n1 + 2*n2;
    for (int i = blockIdx.x*blockDim.x + threadIdx.x; i < total;
         i += gridDim.x*blockDim.x) {
        const float2* src; int off;
        if (i < 4*n1) {
            int w = i / n1; off = i - w*n1;
            src = (const float2*)((w==0)?Wq:(w==1)?Wk:(w==2)?Wv:Wo);
        } else if (i < 4*n1 + n2) {
            src = (const float2*)W1; off = i - 4*n1;
        } else {
            src = (const float2*)W2; off = i - 4*n1 - n2;
        }
        float2 f = src[off];
        ((__half2*)out)[i] = __floats2half2_rn(f.x, f.y);
    }
}

// ---------------------------------------------------------------------------
// LayerNorm: warp-per-row, 8 rows/block, shuffle-only reduction.
// ---------------------------------------------------------------------------
__global__ __launch_bounds__(256) void ln_kernel(
    const float* __restrict__ x, const float* __restrict__ gam,
    const float* __restrict__ bet, __half* __restrict__ out)
{
    int warp = threadIdx.x >> 5, lane = threadIdx.x & 31;
    int row = blockIdx.x * 8 + warp;
    const float4* xr = (const float4*)(x + (size_t)row * D_);

    float4 vv[6];
    float s = 0.f, ss = 0.f;
    #pragma unroll
    for (int c = 0; c < 6; c++) {
        float4 t = xr[c*32 + lane];
        vv[c] = t;
        s  += t.x + t.y + t.z + t.w;
        ss += t.x*t.x + t.y*t.y + t.z*t.z + t.w*t.w;
    }
    #pragma unroll
    for (int o = 16; o > 0; o >>= 1) {
        s  += __shfl_xor_sync(0xffffffffu, s,  o);
        ss += __shfl_xor_sync(0xffffffffu, ss, o);
    }
    float mu  = s * (1.0f / D_);
    float var = ss * (1.0f / D_) - mu * mu;
    float inv = rsqrtf(var + 1e-6f);

    uint2* orow = (uint2*)(out + (size_t)row * D_);
    const float4* gg4 = (const float4*)gam;
    const float4* bb4 = (const float4*)bet;
    #pragma unroll
    for (int c = 0; c < 6; c++) {
        int idx = c*32 + lane;
        float4 gg = gg4[idx], bb = bb4[idx];
        float4 t = vv[c];
        float v0 = (t.x - mu) * inv * gg.x + bb.x;
        float v1 = (t.y - mu) * inv * gg.y + bb.y;
        float v2 = (t.z - mu) * inv * gg.z + bb.z;
        float v3 = (t.w - mu) * inv * gg.w + bb.w;
        uint2 o2;
        o2.x = pack_h2(v0, v1);
        o2.y = pack_h2(v2, v3);
        orow[idx] = o2;
    }
}

// ---------------------------------------------------------------------------
// fp16 tensor-core GEMM: 128x128 tile, BK=64, 256 threads, warp tile 32x64.
// (REVERTED to R10-validated config: 2 CTAs/SM.)
// A: [M][K] fp16, smem [m][k] stride 72, ldmatrix.x4.
// B: natural W [K][N] fp16, smem [k][n] stride 136, ldmatrix.x4.trans.
// 3-stage cp.async pipeline.
// ---------------------------------------------------------------------------
#define BK 64
#define LDAH 72
#define LDBH 136
#define A_STG_H (128*LDAH)        /* 9216 halves */
#define B_STG_H (64*LDBH)         /* 8704 halves */
#define NSTG 3
#define GEMM_SMEM_BYTES (NSTG*(A_STG_H + B_STG_H)*2)   /* 107520 B */

template<int EPI>
__device__ __forceinline__ void h_gemm_body(
    const __half* __restrict__ A, const __half* __restrict__ W,
    const float* __restrict__ bias, const float* __restrict__ res,
    void* __restrict__ Cout, int M, int N, int K)
{
    extern __shared__ __half hsm[];
    __half* As = hsm;
    __half* Bs = hsm + NSTG * A_STG_H;

    int tid  = threadIdx.x;
    int bm = blockIdx.y * 128, bn = blockIdx.x * 128;
    int lane = tid & 31, warp = tid >> 5;
    int warp_m = warp >> 1;
    int warp_n = warp & 1;
    int g  = lane >> 2;
    int tg = lane & 3;

    unsigned a_su[NSTG], b_su[NSTG];
    #pragma unroll
    for (int s = 0; s < NSTG; s++) {
        a_su[s] = (unsigned)__cvta_generic_to_shared(As + s * A_STG_H);
        b_su[s] = (unsigned)__cvta_generic_to_shared(Bs + s * B_STG_H);
    }

    int arow_off = (lane & 7) + ((lane >> 3) & 1) * 8;
    int ak_off   = ((lane >> 4) & 1) * 8;
    unsigned a_lm[2];
    #pragma unroll
    for (int mt = 0; mt < 2; mt++)
        a_lm[mt] = (unsigned)(((warp_m * 32 + mt * 16 + arow_off) * LDAH + ak_off) * 2);

    int trow = (lane & 7) + ((lane >> 3) & 1) * 8;
    int tcol = ((lane >> 4) & 1) * 8;
    unsigned b_lm[4];
    #pragma unroll
    for (int dp = 0; dp < 4; dp++)
        b_lm[dp] = (unsigned)((trow * LDBH + warp_n * 64 + dp * 16 + tcol) * 2);

    float acc[2][8][4];
    #pragma unroll
    for (int mt = 0; mt < 2; mt++)
        #pragma unroll
        for (int nt = 0; nt < 8; nt++)
            #pragma unroll
            for (int i = 0; i < 4; i++) acc[mt][nt][i] = 0.f;

    int nck = K / BK;

    auto issue = [&](int st, int ck) {
        int kb = ck * BK;
        #pragma unroll
        for (int p = 0; p < 4; p++) {
            int cid = tid + p * 256;
            int row = cid >> 3, c = cid & 7;
            unsigned off = (unsigned)((row * LDAH + c * 8) * 2);
            cp_async16(a_su[st] + off, A + (size_t)(bm + row) * K + kb + c * 8);
        }
        #pragma unroll
        for (int p = 0; p < 4; p++) {
            int cid = tid + p * 256;
            int row = cid >> 4, c = cid & 15;
            unsigned off = (unsigned)((row * LDBH + c * 8) * 2);
            cp_async16(b_su[st] + off, W + (size_t)(kb + row) * N + bn + c * 8);
        }
        cp_commit();
    };

    issue(0, 0);
    if (nck > 1) issue(1, 1);

    for (int ck = 0; ck < nck; ck++) {
        int st = ck % 3;
        if (ck + 1 < nck) cp_wait<1>(); else cp_wait<0>();
        __syncthreads();
        if (ck + 2 < nck) issue((ck + 2) % 3, ck + 2);

        unsigned abase = a_su[st], bbase = b_su[st];

        #pragma unroll
        for (int ks = 0; ks < 4; ks++) {
            unsigned kadd_a = (unsigned)(ks * 16 * 2);
            unsigned kadd_b = (unsigned)(ks * 16 * LDBH * 2);
            unsigned af[2][4], bf[8][2];
            #pragma unroll
            for (int mt = 0; mt < 2; mt++)
                ldsm_x4(af[mt][0], af[mt][1], af[mt][2], af[mt][3],
                        abase + a_lm[mt] + kadd_a);
            #pragma unroll
            for (int dp = 0; dp < 4; dp++)
                ldsm_x4_trans(bf[2*dp][0], bf[2*dp][1], bf[2*dp+1][0], bf[2*dp+1][1],
                              bbase + b_lm[dp] + kadd_b);
            #pragma unroll
            for (int mt = 0; mt < 2; mt++)
                #pragma unroll
                for (int nt = 0; nt < 8; nt++)
                    mma_f16(acc[mt][nt], af[mt], bf[nt]);
        }
    }
    __syncthreads();

    #pragma unroll
    for (int mt = 0; mt < 2; mt++) {
        #pragma unroll
        for (int nt = 0; nt < 8; nt++) {
            int row0 = bm + warp_m * 32 + mt * 16 + g;
            int row1 = row0 + 8;
            int col  = bn + warp_n * 64 + nt * 8 + tg * 2;
            float2 bb = *(const float2*)&bias[col];
            float v0 = acc[mt][nt][0] + bb.x;
            float v1 = acc[mt][nt][1] + bb.y;
            float v2 = acc[mt][nt][2] + bb.x;
            float v3 = acc[mt][nt][3] + bb.y;
            if (EPI == EPI_GELU) {
                v0 = gelu_f(v0); v1 = gelu_f(v1);
                v2 = gelu_f(v2); v3 = gelu_f(v3);
            }
            if (EPI == EPI_ADD) {
                float* C = (float*)Cout;
                float2 r0 = *(const float2*)&res[(size_t)row0 * N + col];
                float2 r1 = *(const float2*)&res[(size_t)row1 * N + col];
                v0 += r0.x; v1 += r0.y; v2 += r1.x; v3 += r1.y;
                *(float2*)&C[(size_t)row0 * N + col] = make_float2(v0, v1);
                *(float2*)&C[(size_t)row1 * N + col] = make_float2(v2, v3);
            } else {
                __half* C = (__half*)Cout;
                *(__half2*)&C[(size_t)row0 * N + col] = __floats2half2_rn(v0, v1);
                *(__half2*)&C[(size_t)row1 * N + col] = __floats2half2_rn(v2, v3);
            }
        }
    }
}

template<int EPI>
__global__ __launch_bounds__(256, 2) void h_gemm_kernel(
    const __half* __restrict__ A, const __half* __restrict__ W,
    const float* __restrict__ bias, const float* __restrict__ res,
    void* __restrict__ Cout, int M, int N, int K)
{
    h_gemm_body<EPI>(A, W, bias, res, Cout, M, N, K);
}

__global__ __launch_bounds__(256, 2) void h_qkv_kernel(
    const __half* __restrict__ A, const __half* __restrict__ wt,
    const float* __restrict__ bq, const float* __restrict__ bk, const float* __restrict__ bv,
    __half* __restrict__ Cq, __half* __restrict__ Ck, __half* __restrict__ Cv)
{
    const __half* W   = wt + (size_t)blockIdx.z * (768 * 768);
    const float*  bia = (blockIdx.z == 0) ? bq : (blockIdx.z == 1) ? bk : bv;
    __half*       C   = (blockIdx.z == 0) ? Cq : (blockIdx.z == 1) ? Ck : Cv;
    h_gemm_body<EPI_NONE>(A, W, bia, nullptr, (void*)C, NROWS, D_, D_);
}

// ---------------------------------------------------------------------------
// Fused attention, register flash + cp.async double-buffered K/V,
// ONE barrier per key tile (wait -> barrier -> issue-next -> compute).
// ---------------------------------------------------------------------------
#define LQ 72
struct AttnSmem {
    __half Qh[128][LQ];
    __half Kh[2][64][LQ];
    __half Vh[2][64][LQ];
};
#define ATTN_SMEM_BYTES ((int)sizeof(AttnSmem))

__global__ __launch_bounds__(256) void attn_kernel(
    const __half* __restrict__ q, const __half* __restrict__ k,
    const __half* __restrict__ v, __half* __restrict__ ctx)
{
    extern __shared__ char smem_raw[];
    AttnSmem& S = *(AttnSmem*)smem_raw;
    int bb = blockIdx.z, hh = blockIdx.y;
    int q0 = blockIdx.x * 128;
    int tid = threadIdx.x;
    int lane = tid & 31, wid = tid >> 5;
    int g = lane >> 2, tg = lane & 3;
    int m0 = wid * 16;

    unsigned k_su[2], v_su[2];
    #pragma unroll
    for (int bi = 0; bi < 2; bi++) {
        k_su[bi] = (unsigned)__cvta_generic_to_shared(&S.Kh[bi][0][0]);
        v_su[bi] = (unsigned)__cvta_generic_to_shared(&S.Vh[bi][0][0]);
    }

    auto issue_kv = [&](int bi, int kt) {
        int k0g = kt * 64;
        #pragma unroll
        for (int i = 0; i < 2; i++) {
            int cid = tid + i * 256;
            int row = cid >> 3, c = cid & 7;
            unsigned off = (unsigned)((row * LQ + c * 8) * 2);
            size_t base = ((size_t)((bb*S_ + k0g + row)*H_ + hh))*DH_ + c*8;
            cp_async16(k_su[bi] + off, k + base);
            cp_async16(v_su[bi] + off, v + base);
        }
        cp_commit();
    };

    // load Q (scaled by 1/8)
    {
        const __half2 sc = __half2half2(__float2half(0.125f));
        #pragma unroll
        for (int i = 0; i < 4; i++) {
            int cid = tid + i * 256;
            int row = cid >> 3, c = cid & 7;
            const __half* gq = q + ((size_t)((bb*S_ + q0 + row)*H_ + hh))*DH_ + c*8;
            uint4 t = *(const uint4*)gq;
            __half2* hp = (__half2*)&t;
            #pragma unroll
            for (int j = 0; j < 4; j++) hp[j] = __hmul2(hp[j], sc);
            *(uint4*)&S.Qh[row][c*8] = t;
        }
    }
    issue_kv(0, 0);

    int arow = (lane & 7) + ((lane >> 3) & 1) * 8;
    int acol = ((lane >> 4) & 1) * 8;
    int brow = (lane & 7) + ((lane >> 4) & 1) * 8;
    int bcol = ((lane >> 3) & 1) * 8;

    unsigned q_lm = (unsigned)__cvta_generic_to_shared(&S.Qh[m0 + arow][acol]);
    unsigned k_lm[2][4], v_lm[2][4][4];
    #pragma unroll
    for (int bi = 0; bi < 2; bi++) {
        #pragma unroll
        for (int p = 0; p < 4; p++)
            k_lm[bi][p] = (unsigned)__cvta_generic_to_shared(
                &S.Kh[bi][p*16 + brow][bcol]);
        #pragma unroll
        for (int ks = 0; ks < 4; ks++)
            #pragma unroll
            for (int dp = 0; dp < 4; dp++)
                v_lm[bi][ks][dp] = (unsigned)__cvta_generic_to_shared(
                    &S.Vh[bi][ks*16 + arow][dp*16 + acol]);
    }

    float m_r[2] = {-1e30f, -1e30f};
    float l_r[2] = {0.f, 0.f};
    float o[8][4];
    #pragma unroll
    for (int nt = 0; nt < 8; nt++)
        #pragma unroll
        for (int i = 0; i < 4; i++) o[nt][i] = 0.f;

    __syncthreads();

    unsigned aq[4][4];
    #pragma unroll
    for (int ks = 0; ks < 4; ks++)
        ldsm_x4(aq[ks][0], aq[ks][1], aq[ks][2], aq[ks][3], q_lm + ks*32);

    const int NKT = S_/64;
    for (int kt = 0; kt < NKT; kt++) {
        int bi = kt & 1;
        // tile kt was issued one iteration ago; wait for it.
        cp_wait<0>();
        // Single barrier: (a) tile kt visible to all, (b) all warps have
        // finished reading buffer bi^1 (they passed last iteration's compute).
        __syncthreads();
        // Now safe to overwrite buffer bi^1 with tile kt+1.
        if (kt + 1 < NKT) issue_kv(bi ^ 1, kt + 1);

        // ---- QK^T ----
        float s[8][4];
        #pragma unroll
        for (int nt = 0; nt < 8; nt++)
            #pragma unroll
            for (int i = 0; i < 4; i++) s[nt][i] = 0.f;
        #pragma unroll
        for (int ks = 0; ks < 4; ks++) {
            unsigned bf[8][2];
            #pragma unroll
            for (int p = 0; p < 4; p++)
                ldsm_x4(bf[2*p][0], bf[2*p][1], bf[2*p+1][0], bf[2*p+1][1],
                        k_lm[bi][p] + ks*32);
            #pragma unroll
            for (int nt = 0; nt < 8; nt++)
                mma_f16(s[nt], aq[ks], bf[nt]);
        }

        // ---- warp-local online softmax ----
        #pragma unroll
        for (int r = 0; r < 2; r++) {
            float mx = -1e30f;
            #pragma unroll
            for (int nt = 0; nt < 8; nt++)
                mx = fmaxf(mx, fmaxf(s[nt][2*r], s[nt][2*r+1]));
            mx = fmaxf(mx, __shfl_xor_sync(0xffffffffu, mx, 1));
            mx = fmaxf(mx, __shfl_xor_sync(0xffffffffu, mx, 2));
            float mn = fmaxf(m_r[r], mx);
            float cr = __expf(m_r[r] - mn);
            m_r[r] = mn;
            float ls = 0.f;
            #pragma unroll
            for (int nt = 0; nt < 8; nt++) {
                float p0 = __expf(s[nt][2*r    ] - mn);
                float p1 = __expf(s[nt][2*r + 1] - mn);
                s[nt][2*r] = p0; s[nt][2*r+1] = p1;
                ls += p0 + p1;
            }
            ls += __shfl_xor_sync(0xffffffffu, ls, 1);
            ls += __shfl_xor_sync(0xffffffffu, ls, 2);
            l_r[r] = l_r[r] * cr + ls;
            #pragma unroll
            for (int nt = 0; nt < 8; nt++) {
                o[nt][2*r] *= cr; o[nt][2*r+1] *= cr;
            }
        }

        unsigned pa[4][4];
        #pragma unroll
        for (int ks = 0; ks < 4; ks++) {
            pa[ks][0] = pack_h2(s[2*ks  ][0], s[2*ks  ][1]);
            pa[ks][1] = pack_h2(s[2*ks  ][2], s[2*ks  ][3]);
            pa[ks][2] = pack_h2(s[2*ks+1][0], s[2*ks+1][1]);
            pa[ks][3] = pack_h2(s[2*ks+1][2], s[2*ks+1][3]);
        }

        // ---- P*V ----
        #pragma unroll
        for (int ks = 0; ks < 4; ks++) {
            unsigned vf[8][2];
            #pragma unroll
            for (int dp = 0; dp < 4; dp++)
                ldsm_x4_trans(vf[2*dp][0], vf[2*dp][1], vf[2*dp+1][0], vf[2*dp+1][1],
                              v_lm[bi][ks][dp]);
            #pragma unroll
            for (int nt = 0; nt < 8; nt++)
                mma_f16(o[nt], pa[ks], vf[nt]);
        }
        // no trailing barrier: next iteration's barrier covers buffer reuse
    }

    float inv0 = 1.0f / l_r[0];
    float inv1 = 1.0f / l_r[1];
    int row0 = bb*S_ + q0 + m0 + g;
    int row1 = row0 + 8;
    #pragma unroll
    for (int nt = 0; nt < 8; nt++) {
        int d = nt * 8 + tg * 2;
        *(__half2*)&ctx[((size_t)(row0*H_ + hh))*DH_ + d] =
            __floats2half2_rn(o[nt][0] * inv0, o[nt][1] * inv0);
        *(__half2*)&ctx[((size_t)(row1*H_ + hh))*DH_ + d] =
            __floats2half2_rn(o[nt][2] * inv1, o[nt][3] * inv1);
    }
}

// ---------------------------------------------------------------------------
// Launcher
// ---------------------------------------------------------------------------
extern "C" void kernel_launch(void* const* d_in, const int* in_sizes, int n_in,
                              void* d_out, int out_size)
{
    const float* x   = (const float*)d_in[0];
    const float* Wq  = (const float*)d_in[1];
    const float* bq  = (const float*)d_in[2];
    const float* Wk  = (const float*)d_in[3];
    const float* bk  = (const float*)d_in[4];
    const float* Wv  = (const float*)d_in[5];
    const float* bv  = (const float*)d_in[6];
    const float* Wo  = (const float*)d_in[7];
    const float* bo  = (const float*)d_in[8];
    const float* g1  = (const float*)d_in[9];
    const float* be1 = (const float*)d_in[10];
    const float* g2  = (const float*)d_in[11];
    const float* be2 = (const float*)d_in[12];
    const float* W1  = (const float*)d_in[13];
    const float* b1  = (const float*)d_in[14];
    const float* W2  = (const float*)d_in[15];
    const float* b2  = (const float*)d_in[16];
    float* out = (float*)d_out;

    __half *h, *q, *k, *v, *ctx, *ln2, *act, *wt;
    float *x2;
    cudaGetSymbolAddress((void**)&h,   g_h);
    cudaGetSymbolAddress((void**)&q,   g_q);
    cudaGetSymbolAddress((void**)&k,   g_k);
    cudaGetSymbolAddress((void**)&v,   g_v);
    cudaGetSymbolAddress((void**)&ctx, g_ctx);
    cudaGetSymbolAddress((void**)&x2,  g_x2);
    cudaGetSymbolAddress((void**)&ln2, g_ln2);
    cudaGetSymbolAddress((void**)&act, g_act);
    cudaGetSymbolAddress((void**)&wt,  g_wt);

    cudaFuncSetAttribute(h_gemm_kernel<EPI_ADD>,
                         cudaFuncAttributeMaxDynamicSharedMemorySize, GEMM_SMEM_BYTES);
    cudaFuncSetAttribute(h_gemm_kernel<EPI_GELU>,
                         cudaFuncAttributeMaxDynamicSharedMemorySize, GEMM_SMEM_BYTES);
    cudaFuncSetAttribute(h_qkv_kernel,
                         cudaFuncAttributeMaxDynamicSharedMemorySize, GEMM_SMEM_BYTES);
    cudaFuncSetAttribute(attn_kernel,
                         cudaFuncAttributeMaxDynamicSharedMemorySize, ATTN_SMEM_BYTES);

    // 0. weight fp32->fp16 convert (natural layout), single launch
    convert_w_kernel<<<2048, 256>>>(Wq, Wk, Wv, Wo, W1, W2, wt);

    // 1. pre-LN -> fp16 h
    ln_kernel<<<NROWS/8, 256>>>(x, g1, be1, h);
    // 2. QKV (fp16 mma, batched) -> fp16 q,k,v
    dim3 gqkv(D_/128, NROWS/128, 3);
    h_qkv_kernel<<<gqkv, 256, GEMM_SMEM_BYTES>>>(h, wt, bq, bk, bv, q, k, v);
    // 3. fused attention -> fp16 ctx
    dim3 gat(S_/128, H_, B_);
    attn_kernel<<<gat, 256, ATTN_SMEM_BYTES>>>(q, k, v, ctx);
    // 4. Wo projection + residual -> fp32 x2
    dim3 go(D_/128, NROWS/128);
    h_gemm_kernel<EPI_ADD><<<go, 256, GEMM_SMEM_BYTES>>>(ctx, wt + WT_O, bo, x, (void*)x2, NROWS, D_, D_);
    // 5. LN2 -> fp16 ln2
    ln_kernel<<<NROWS/8, 256>>>(x2, g2, be2, ln2);
    // 6. MLP up + exact GELU -> fp16 act
    dim3 gup(F_/128, NROWS/128);
    h_gemm_kernel<EPI_GELU><<<gup, 256, GEMM_SMEM_BYTES>>>(ln2, wt + WT_W1, b1, nullptr, (void*)act, NROWS, F_, D_);
    // 7. MLP down + bias + residual -> fp32 out
    dim3 gdn(D_/128, NROWS/128);
    h_gemm_kernel<EPI_ADD><<<gdn, 256, GEMM_SMEM_BYTES>>>(act, wt + WT_W2, b2, x2, (void*)out, NROWS, D_, F_);
}